// round 7
// baseline (speedup 1.0000x reference)
#include <cuda_runtime.h>

#define N_NODES 50000
#define N_EDGES 800000
#define IN_F 96
#define HID 64
#define N_CLS 32

// Scratch (__device__ globals, allocation-free rule)
__device__ __align__(16) float g_y[N_NODES * HID];     // x @ W1       (12.8 MB)
__device__ __align__(16) float g_z[N_NODES * N_CLS];   // relu(.)@W2   ( 6.4 MB)
__device__ int g_cnt[N_NODES];
__device__ int g_off[N_NODES + 1];
__device__ int g_cur[N_NODES];
__device__ int g_ssrc[N_EDGES];

// ---------------- CSR build ----------------

__global__ void hist_kernel(const int* __restrict__ dst) {
    int i = blockIdx.x * blockDim.x + threadIdx.x;
    if (i < N_EDGES) atomicAdd(&g_cnt[dst[i]], 1);
}

// Single-block exclusive scan of g_cnt -> g_off, g_cur. blockDim = 1024.
__global__ void scan_kernel() {
    __shared__ int sh[1024];
    const int C = (N_NODES + 1023) / 1024;   // 49
    int t = threadIdx.x;
    int base = t * C;
    int s = 0;
    for (int j = 0; j < C; ++j) {
        int idx = base + j;
        if (idx < N_NODES) s += g_cnt[idx];
    }
    sh[t] = s;
    __syncthreads();
    for (int o = 1; o < 1024; o <<= 1) {
        int v = (t >= o) ? sh[t - o] : 0;
        __syncthreads();
        sh[t] += v;
        __syncthreads();
    }
    int run = sh[t] - s;
    for (int j = 0; j < C; ++j) {
        int idx = base + j;
        if (idx < N_NODES) {
            int c = g_cnt[idx];
            g_off[idx] = run;
            g_cur[idx] = run;
            run += c;
        }
    }
    if (t == 1023) g_off[N_NODES] = N_EDGES;
}

__global__ void reorder_kernel(const int* __restrict__ src,
                               const int* __restrict__ dst) {
    int i = blockIdx.x * blockDim.x + threadIdx.x;
    if (i < N_EDGES) {
        int pos = atomicAdd(&g_cur[dst[i]], 1);
        g_ssrc[pos] = src[i];
    }
}

// ---------------- compute ----------------

// y = x @ W1  [50000 x 64]. 50 nodes/block, 160 threads, 5x4 register tile.
// Also zeroes g_cnt (1000 blocks x 160 threads = 160k >= 50k).
__global__ void __launch_bounds__(160) gemm_x_kernel(
        const float* __restrict__ x,
        const float* __restrict__ W1,
        float* __restrict__ Y) {
    __shared__ float xs[50 * 100];
    __shared__ float ws[IN_F * HID];
    int tid = threadIdx.x;

    int gi = blockIdx.x * 160 + tid;
    if (gi < N_NODES) g_cnt[gi] = 0;

    for (int i = tid; i < IN_F * HID / 4; i += 160)
        ((float4*)ws)[i] = __ldg((const float4*)W1 + i);

    const float4* xg = (const float4*)x + blockIdx.x * 50 * (IN_F / 4);
    for (int i = tid; i < 50 * (IN_F / 4); i += 160) {
        int r = i / (IN_F / 4);
        int c = i - r * (IN_F / 4);
        *(float4*)&xs[r * 100 + c * 4] = __ldg(xg + i);
    }
    __syncthreads();

    int tx = tid & 15;
    int ty = tid >> 4;
    float acc[5][4];
#pragma unroll
    for (int i = 0; i < 5; ++i)
#pragma unroll
        for (int j = 0; j < 4; ++j) acc[i][j] = 0.f;

    const float* xbase = &xs[ty * 5 * 100];
#pragma unroll 2
    for (int k = 0; k < IN_F; k += 4) {
        float4 wv0 = *(float4*)&ws[(k + 0) * HID + tx * 4];
        float4 wv1 = *(float4*)&ws[(k + 1) * HID + tx * 4];
        float4 wv2 = *(float4*)&ws[(k + 2) * HID + tx * 4];
        float4 wv3 = *(float4*)&ws[(k + 3) * HID + tx * 4];
#pragma unroll
        for (int i = 0; i < 5; ++i) {
            float4 xv = *(float4*)&xbase[i * 100 + k];
            acc[i][0] = fmaf(xv.x, wv0.x, acc[i][0]);
            acc[i][1] = fmaf(xv.x, wv0.y, acc[i][1]);
            acc[i][2] = fmaf(xv.x, wv0.z, acc[i][2]);
            acc[i][3] = fmaf(xv.x, wv0.w, acc[i][3]);
            acc[i][0] = fmaf(xv.y, wv1.x, acc[i][0]);
            acc[i][1] = fmaf(xv.y, wv1.y, acc[i][1]);
            acc[i][2] = fmaf(xv.y, wv1.z, acc[i][2]);
            acc[i][3] = fmaf(xv.y, wv1.w, acc[i][3]);
            acc[i][0] = fmaf(xv.z, wv2.x, acc[i][0]);
            acc[i][1] = fmaf(xv.z, wv2.y, acc[i][1]);
            acc[i][2] = fmaf(xv.z, wv2.z, acc[i][2]);
            acc[i][3] = fmaf(xv.z, wv2.w, acc[i][3]);
            acc[i][0] = fmaf(xv.w, wv3.x, acc[i][0]);
            acc[i][1] = fmaf(xv.w, wv3.y, acc[i][1]);
            acc[i][2] = fmaf(xv.w, wv3.z, acc[i][2]);
            acc[i][3] = fmaf(xv.w, wv3.w, acc[i][3]);
        }
    }
    int n0 = blockIdx.x * 50 + ty * 5;
#pragma unroll
    for (int i = 0; i < 5; ++i)
        *(float4*)&Y[(n0 + i) * HID + tx * 4] =
            make_float4(acc[i][0], acc[i][1], acc[i][2], acc[i][3]);
}

// Layer 1 fused: gather y over in-edges (CSR), relu(+b1), then h @ W2 -> Z.
// 64 nodes/block, 256 threads. Gather: thread = (chunk c of 16, node slice).
__global__ void __launch_bounds__(256) layer1_kernel(
        const float* __restrict__ b1,
        const float* __restrict__ W2,
        float* __restrict__ Z) {
    __shared__ float as[64 * 68];      // 17408 B
    __shared__ float ws[HID * N_CLS];  // 8192 B
    int tid = threadIdx.x;

    for (int i = tid; i < HID * N_CLS / 4; i += 256)
        ((float4*)ws)[i] = __ldg((const float4*)W2 + i);

    int n0 = blockIdx.x * 64;
    int c = tid & 15;        // float4 chunk within the 64-wide row
    int r0 = tid >> 4;       // 0..15; handles nodes r0, r0+16, r0+32, r0+48
    const float4* y4 = (const float4*)g_y;
    float4 bb = __ldg((const float4*)b1 + c);

#pragma unroll
    for (int rr = r0; rr < 64; rr += 16) {
        int n = n0 + rr;
        float4 acc = make_float4(0.f, 0.f, 0.f, 0.f);
        if (n < N_NODES) {
            int e = g_off[n], end = g_off[n + 1];
            for (; e + 4 <= end; e += 4) {
                int s0 = __ldg(g_ssrc + e + 0);
                int s1 = __ldg(g_ssrc + e + 1);
                int s2 = __ldg(g_ssrc + e + 2);
                int s3 = __ldg(g_ssrc + e + 3);
                float4 v0 = __ldg(y4 + s0 * 16 + c);
                float4 v1 = __ldg(y4 + s1 * 16 + c);
                float4 v2 = __ldg(y4 + s2 * 16 + c);
                float4 v3 = __ldg(y4 + s3 * 16 + c);
                acc.x += (v0.x + v1.x) + (v2.x + v3.x);
                acc.y += (v0.y + v1.y) + (v2.y + v3.y);
                acc.z += (v0.z + v1.z) + (v2.z + v3.z);
                acc.w += (v0.w + v1.w) + (v2.w + v3.w);
            }
            for (; e < end; ++e) {
                int s = __ldg(g_ssrc + e);
                float4 v = __ldg(y4 + s * 16 + c);
                acc.x += v.x; acc.y += v.y; acc.z += v.z; acc.w += v.w;
            }
        }
        float4 h;
        h.x = fmaxf(acc.x + bb.x, 0.f);
        h.y = fmaxf(acc.y + bb.y, 0.f);
        h.z = fmaxf(acc.z + bb.z, 0.f);
        h.w = fmaxf(acc.w + bb.w, 0.f);
        *(float4*)&as[rr * 68 + c * 4] = h;
    }
    __syncthreads();

    int tx = tid & 7;
    int ty = tid >> 3;
    float acc[2][4];
#pragma unroll
    for (int i = 0; i < 2; ++i)
#pragma unroll
        for (int j = 0; j < 4; ++j) acc[i][j] = 0.f;

    const float* abase = &as[ty * 2 * 68];
#pragma unroll 4
    for (int k = 0; k < HID; k += 4) {
        float4 wv0 = *(float4*)&ws[(k + 0) * N_CLS + tx * 4];
        float4 wv1 = *(float4*)&ws[(k + 1) * N_CLS + tx * 4];
        float4 wv2 = *(float4*)&ws[(k + 2) * N_CLS + tx * 4];
        float4 wv3 = *(float4*)&ws[(k + 3) * N_CLS + tx * 4];
#pragma unroll
        for (int i = 0; i < 2; ++i) {
            float4 xv = *(float4*)&abase[i * 68 + k];
            acc[i][0] = fmaf(xv.x, wv0.x, acc[i][0]);
            acc[i][1] = fmaf(xv.x, wv0.y, acc[i][1]);
            acc[i][2] = fmaf(xv.x, wv0.z, acc[i][2]);
            acc[i][3] = fmaf(xv.x, wv0.w, acc[i][3]);
            acc[i][0] = fmaf(xv.y, wv1.x, acc[i][0]);
            acc[i][1] = fmaf(xv.y, wv1.y, acc[i][1]);
            acc[i][2] = fmaf(xv.y, wv1.z, acc[i][2]);
            acc[i][3] = fmaf(xv.y, wv1.w, acc[i][3]);
            acc[i][0] = fmaf(xv.z, wv2.x, acc[i][0]);
            acc[i][1] = fmaf(xv.z, wv2.y, acc[i][1]);
            acc[i][2] = fmaf(xv.z, wv2.z, acc[i][2]);
            acc[i][3] = fmaf(xv.z, wv2.w, acc[i][3]);
            acc[i][0] = fmaf(xv.w, wv3.x, acc[i][0]);
            acc[i][1] = fmaf(xv.w, wv3.y, acc[i][1]);
            acc[i][2] = fmaf(xv.w, wv3.z, acc[i][2]);
            acc[i][3] = fmaf(xv.w, wv3.w, acc[i][3]);
        }
    }
#pragma unroll
    for (int i = 0; i < 2; ++i) {
        int n = n0 + ty * 2 + i;
        if (n < N_NODES)
            *(float4*)&Z[n * N_CLS + tx * 4] =
                make_float4(acc[i][0], acc[i][1], acc[i][2], acc[i][3]);
    }
}

// Layer 2 fused: gather z over in-edges, +b2, log_softmax -> out.
// 32 nodes/block, 256 threads; thread = (node group of 8 lanes, chunk c of 8).
__global__ void __launch_bounds__(256) layer2_kernel(
        const float* __restrict__ b2,
        float* __restrict__ out) {
    int tid = threadIdx.x;
    int c = tid & 7;
    int grp = tid >> 3;                 // 0..31
    int n = blockIdx.x * 32 + grp;
    const float4* z4 = (const float4*)g_z;
    float4 bb = __ldg((const float4*)b2 + c);

    float4 acc = make_float4(0.f, 0.f, 0.f, 0.f);
    if (n < N_NODES) {
        int e = g_off[n], end = g_off[n + 1];
        for (; e + 4 <= end; e += 4) {
            int s0 = __ldg(g_ssrc + e + 0);
            int s1 = __ldg(g_ssrc + e + 1);
            int s2 = __ldg(g_ssrc + e + 2);
            int s3 = __ldg(g_ssrc + e + 3);
            float4 v0 = __ldg(z4 + s0 * 8 + c);
            float4 v1 = __ldg(z4 + s1 * 8 + c);
            float4 v2 = __ldg(z4 + s2 * 8 + c);
            float4 v3 = __ldg(z4 + s3 * 8 + c);
            acc.x += (v0.x + v1.x) + (v2.x + v3.x);
            acc.y += (v0.y + v1.y) + (v2.y + v3.y);
            acc.z += (v0.z + v1.z) + (v2.z + v3.z);
            acc.w += (v0.w + v1.w) + (v2.w + v3.w);
        }
        for (; e < end; ++e) {
            int s = __ldg(g_ssrc + e);
            float4 v = __ldg(z4 + s * 8 + c);
            acc.x += v.x; acc.y += v.y; acc.z += v.z; acc.w += v.w;
        }
    }
    acc.x += bb.x; acc.y += bb.y; acc.z += bb.z; acc.w += bb.w;

    // log_softmax over 32 classes spread across 8 lanes x 4 elements.
    float m = fmaxf(fmaxf(acc.x, acc.y), fmaxf(acc.z, acc.w));
#pragma unroll
    for (int o = 1; o <= 4; o <<= 1) m = fmaxf(m, __shfl_xor_sync(0xffffffffu, m, o));
    float p = __expf(acc.x - m) + __expf(acc.y - m) + __expf(acc.z - m) + __expf(acc.w - m);
#pragma unroll
    for (int o = 1; o <= 4; o <<= 1) p += __shfl_xor_sync(0xffffffffu, p, o);
    float lp = m + __logf(p);

    if (n < N_NODES) {
        float4 r;
        r.x = acc.x - lp; r.y = acc.y - lp; r.z = acc.z - lp; r.w = acc.w - lp;
        ((float4*)out)[n * 8 + c] = r;
    }
}

extern "C" void kernel_launch(void* const* d_in, const int* in_sizes, int n_in,
                              void* d_out, int out_size) {
    const float* x  = (const float*)d_in[0];
    const int*   ei = (const int*)d_in[1];   // int32 [2, E]
    const float* W1 = (const float*)d_in[2];
    const float* b1 = (const float*)d_in[3];
    const float* W2 = (const float*)d_in[4];
    const float* b2 = (const float*)d_in[5];
    float* out      = (float*)d_out;

    const int* src = ei;
    const int* dst = ei + N_EDGES;

    float* y; cudaGetSymbolAddress((void**)&y, g_y);
    float* z; cudaGetSymbolAddress((void**)&z, g_z);

    // 1. y = x @ W1 (also zeroes g_cnt; completes before hist launches)
    gemm_x_kernel<<<N_NODES / 50, 160>>>(x, W1, y);

    // 2-4. CSR build (by dst)
    hist_kernel<<<(N_EDGES + 255) / 256, 256>>>(dst);
    scan_kernel<<<1, 1024>>>();
    reorder_kernel<<<(N_EDGES + 255) / 256, 256>>>(src, dst);

    // 5. layer 1: gather + relu + @W2 fused
    layer1_kernel<<<(N_NODES + 63) / 64, 256>>>(b1, W2, z);

    // 6. layer 2: gather + bias + log_softmax fused
    layer2_kernel<<<(N_NODES + 31) / 32, 256>>>(b2, out);
}

// round 8
// speedup vs baseline: 1.8530x; 1.8530x over previous
#include <cuda_runtime.h>
#include <cuda_fp16.h>

#define N_NODES 50000
#define N_EDGES 800000
#define IN_F 96
#define HID 64
#define N_CLS 32

// Scratch (__device__ globals, allocation-free rule)
__device__ __align__(16) unsigned g_yh[N_NODES * (HID / 2)];    // y as half2   (6.4 MB)
__device__ __align__(16) unsigned g_agg1h[N_NODES * (HID / 2)]; // agg1 half2   (6.4 MB)
__device__ __align__(16) float g_z[N_NODES * N_CLS];            // relu(.)@W2   (6.4 MB)
__device__ __align__(16) float g_agg2[N_NODES * N_CLS];         // agg2 f32     (6.4 MB)

__device__ __forceinline__ void red_add_v4f(float* p, float4 v) {
    asm volatile("red.global.add.v4.f32 [%0], {%1,%2,%3,%4};"
                 :: "l"(p), "f"(v.x), "f"(v.y), "f"(v.z), "f"(v.w) : "memory");
}
__device__ __forceinline__ void red_add_v4h2(unsigned* p, uint4 v) {
    asm volatile("red.global.add.noftz.v4.f16x2 [%0], {%1,%2,%3,%4};"
                 :: "l"(p), "r"(v.x), "r"(v.y), "r"(v.z), "r"(v.w) : "memory");
}

// Zero agg1h (400k uint4) + agg2 (400k float4). 0x0000 == +0.0h.
__global__ void zero_kernel() {
    const int n1 = N_NODES * (HID / 2) / 4;   // uint4 count = 400000
    const int n2 = N_NODES * N_CLS / 4;       // float4 count = 400000
    int i = blockIdx.x * blockDim.x + threadIdx.x;
    if (i < n1) ((uint4*)g_agg1h)[i] = make_uint4(0u, 0u, 0u, 0u);
    else if (i < n1 + n2) ((float4*)g_agg2)[i - n1] = make_float4(0.f, 0.f, 0.f, 0.f);
}

// y = x @ W1 [50000 x 64], output packed half2. 50 nodes/block, 160 threads,
// thread computes 5 nodes x 4 cols (= 2 half2).
__global__ void __launch_bounds__(160) gemm_x_kernel(
        const float* __restrict__ x,
        const float* __restrict__ W1) {
    __shared__ float xs[50 * 100];
    __shared__ float ws[IN_F * HID];
    int tid = threadIdx.x;

    for (int i = tid; i < IN_F * HID / 4; i += 160)
        ((float4*)ws)[i] = __ldg((const float4*)W1 + i);

    const float4* xg = (const float4*)x + blockIdx.x * 50 * (IN_F / 4);
    for (int i = tid; i < 50 * (IN_F / 4); i += 160) {
        int r = i / (IN_F / 4);
        int c = i - r * (IN_F / 4);
        *(float4*)&xs[r * 100 + c * 4] = __ldg(xg + i);
    }
    __syncthreads();

    int tx = tid & 15;
    int ty = tid >> 4;
    float acc[5][4];
#pragma unroll
    for (int i = 0; i < 5; ++i)
#pragma unroll
        for (int j = 0; j < 4; ++j) acc[i][j] = 0.f;

    const float* xbase = &xs[ty * 5 * 100];
#pragma unroll 2
    for (int k = 0; k < IN_F; k += 4) {
        float4 wv0 = *(float4*)&ws[(k + 0) * HID + tx * 4];
        float4 wv1 = *(float4*)&ws[(k + 1) * HID + tx * 4];
        float4 wv2 = *(float4*)&ws[(k + 2) * HID + tx * 4];
        float4 wv3 = *(float4*)&ws[(k + 3) * HID + tx * 4];
#pragma unroll
        for (int i = 0; i < 5; ++i) {
            float4 xv = *(float4*)&xbase[i * 100 + k];
            acc[i][0] = fmaf(xv.x, wv0.x, acc[i][0]);
            acc[i][1] = fmaf(xv.x, wv0.y, acc[i][1]);
            acc[i][2] = fmaf(xv.x, wv0.z, acc[i][2]);
            acc[i][3] = fmaf(xv.x, wv0.w, acc[i][3]);
            acc[i][0] = fmaf(xv.y, wv1.x, acc[i][0]);
            acc[i][1] = fmaf(xv.y, wv1.y, acc[i][1]);
            acc[i][2] = fmaf(xv.y, wv1.z, acc[i][2]);
            acc[i][3] = fmaf(xv.y, wv1.w, acc[i][3]);
            acc[i][0] = fmaf(xv.z, wv2.x, acc[i][0]);
            acc[i][1] = fmaf(xv.z, wv2.y, acc[i][1]);
            acc[i][2] = fmaf(xv.z, wv2.z, acc[i][2]);
            acc[i][3] = fmaf(xv.z, wv2.w, acc[i][3]);
            acc[i][0] = fmaf(xv.w, wv3.x, acc[i][0]);
            acc[i][1] = fmaf(xv.w, wv3.y, acc[i][1]);
            acc[i][2] = fmaf(xv.w, wv3.z, acc[i][2]);
            acc[i][3] = fmaf(xv.w, wv3.w, acc[i][3]);
        }
    }
    int n0 = blockIdx.x * 50 + ty * 5;
#pragma unroll
    for (int i = 0; i < 5; ++i) {
        __half2 h0 = __floats2half2_rn(acc[i][0], acc[i][1]);
        __half2 h1 = __floats2half2_rn(acc[i][2], acc[i][3]);
        uint2 u;
        u.x = *(unsigned*)&h0;
        u.y = *(unsigned*)&h1;
        *(uint2*)&g_yh[(n0 + i) * (HID / 2) + tx * 2] = u;
    }
}

// Layer-1 scatter: agg1h[dst] += yh[src]; 64 halves = 8 x uint4 lanes per edge.
__global__ void scatter_h_kernel(const int* __restrict__ src,
                                 const int* __restrict__ dst) {
    int i = blockIdx.x * blockDim.x + threadIdx.x;
    int e = i >> 3;
    int c = i & 7;
    int s = __ldg(src + e);
    int d = __ldg(dst + e);
    uint4 v = __ldg((const uint4*)g_yh + s * 8 + c);
    red_add_v4h2(g_agg1h + d * (HID / 2) + c * 4, v);
}

// Layer-2 scatter: agg2[dst] += z[src]; 32 floats = 8 float4 lanes per edge.
__global__ void scatter_f_kernel(const int* __restrict__ src,
                                 const int* __restrict__ dst) {
    int i = blockIdx.x * blockDim.x + threadIdx.x;
    int e = i >> 3;
    int c = i & 7;
    int s = __ldg(src + e);
    int d = __ldg(dst + e);
    float4 v = __ldg((const float4*)g_z + s * 8 + c);
    red_add_v4f(g_agg2 + d * N_CLS + 4 * c, v);
}

// z = relu(agg1 + b1) @ W2  [50000 x 32]. 64 nodes/block, 256 threads,
// 2x4 register tile. half2->float conversion + relu + bias fused in staging.
__global__ void __launch_bounds__(256) hidden_kernel(
        const float* __restrict__ b1,
        const float* __restrict__ W2,
        float* __restrict__ Z) {
    __shared__ float as[64 * 68];      // 17408 B
    __shared__ float ws[HID * N_CLS];  // 8192 B
    int tid = threadIdx.x;

    for (int i = tid; i < HID * N_CLS / 4; i += 256)
        ((float4*)ws)[i] = __ldg((const float4*)W2 + i);

    int n0 = blockIdx.x * 64;
    // stage: 64 rows x 8 chunks (8 halves each) = 512 items
    for (int i = tid; i < 64 * 8; i += 256) {
        int r = i >> 3;
        int c = i & 7;
        int n = n0 + r;
        float4 f0 = make_float4(0.f, 0.f, 0.f, 0.f);
        float4 f1 = f0;
        if (n < N_NODES) {
            uint4 u = __ldg((const uint4*)g_agg1h + n * 8 + c);
            float2 a0 = __half22float2(*(__half2*)&u.x);
            float2 a1 = __half22float2(*(__half2*)&u.y);
            float2 a2 = __half22float2(*(__half2*)&u.z);
            float2 a3 = __half22float2(*(__half2*)&u.w);
            float4 bb0 = __ldg((const float4*)b1 + c * 2);
            float4 bb1 = __ldg((const float4*)b1 + c * 2 + 1);
            f0.x = fmaxf(a0.x + bb0.x, 0.f);
            f0.y = fmaxf(a0.y + bb0.y, 0.f);
            f0.z = fmaxf(a1.x + bb0.z, 0.f);
            f0.w = fmaxf(a1.y + bb0.w, 0.f);
            f1.x = fmaxf(a2.x + bb1.x, 0.f);
            f1.y = fmaxf(a2.y + bb1.y, 0.f);
            f1.z = fmaxf(a3.x + bb1.z, 0.f);
            f1.w = fmaxf(a3.y + bb1.w, 0.f);
        }
        *(float4*)&as[r * 68 + c * 8]     = f0;
        *(float4*)&as[r * 68 + c * 8 + 4] = f1;
    }
    __syncthreads();

    int tx = tid & 7;
    int ty = tid >> 3;
    float acc[2][4];
#pragma unroll
    for (int i = 0; i < 2; ++i)
#pragma unroll
        for (int j = 0; j < 4; ++j) acc[i][j] = 0.f;

    const float* abase = &as[ty * 2 * 68];
#pragma unroll 4
    for (int k = 0; k < HID; k += 4) {
        float4 wv0 = *(float4*)&ws[(k + 0) * N_CLS + tx * 4];
        float4 wv1 = *(float4*)&ws[(k + 1) * N_CLS + tx * 4];
        float4 wv2 = *(float4*)&ws[(k + 2) * N_CLS + tx * 4];
        float4 wv3 = *(float4*)&ws[(k + 3) * N_CLS + tx * 4];
#pragma unroll
        for (int i = 0; i < 2; ++i) {
            float4 xv = *(float4*)&abase[i * 68 + k];
            acc[i][0] = fmaf(xv.x, wv0.x, acc[i][0]);
            acc[i][1] = fmaf(xv.x, wv0.y, acc[i][1]);
            acc[i][2] = fmaf(xv.x, wv0.z, acc[i][2]);
            acc[i][3] = fmaf(xv.x, wv0.w, acc[i][3]);
            acc[i][0] = fmaf(xv.y, wv1.x, acc[i][0]);
            acc[i][1] = fmaf(xv.y, wv1.y, acc[i][1]);
            acc[i][2] = fmaf(xv.y, wv1.z, acc[i][2]);
            acc[i][3] = fmaf(xv.y, wv1.w, acc[i][3]);
            acc[i][0] = fmaf(xv.z, wv2.x, acc[i][0]);
            acc[i][1] = fmaf(xv.z, wv2.y, acc[i][1]);
            acc[i][2] = fmaf(xv.z, wv2.z, acc[i][2]);
            acc[i][3] = fmaf(xv.z, wv2.w, acc[i][3]);
            acc[i][0] = fmaf(xv.w, wv3.x, acc[i][0]);
            acc[i][1] = fmaf(xv.w, wv3.y, acc[i][1]);
            acc[i][2] = fmaf(xv.w, wv3.z, acc[i][2]);
            acc[i][3] = fmaf(xv.w, wv3.w, acc[i][3]);
        }
    }
#pragma unroll
    for (int i = 0; i < 2; ++i) {
        int n = n0 + ty * 2 + i;
        if (n < N_NODES)
            *(float4*)&Z[n * N_CLS + tx * 4] =
                make_float4(acc[i][0], acc[i][1], acc[i][2], acc[i][3]);
    }
}

// out = log_softmax(agg2 + b2). One warp per node (lane = class), 8 nodes/block.
__global__ void lsm_kernel(const float* __restrict__ b2,
                           float* __restrict__ out) {
    int lane = threadIdx.x & 31;
    int n = blockIdx.x * 8 + (threadIdx.x >> 5);
    float acc = g_agg2[n * N_CLS + lane] + __ldg(b2 + lane);
    float m = acc;
#pragma unroll
    for (int o = 16; o; o >>= 1) m = fmaxf(m, __shfl_xor_sync(0xffffffffu, m, o));
    float p = __expf(acc - m);
#pragma unroll
    for (int o = 16; o; o >>= 1) p += __shfl_xor_sync(0xffffffffu, p, o);
    out[n * N_CLS + lane] = acc - m - __logf(p);
}

extern "C" void kernel_launch(void* const* d_in, const int* in_sizes, int n_in,
                              void* d_out, int out_size) {
    const float* x  = (const float*)d_in[0];
    const int*   ei = (const int*)d_in[1];   // int32 [2, E]
    const float* W1 = (const float*)d_in[2];
    const float* b1 = (const float*)d_in[3];
    const float* W2 = (const float*)d_in[4];
    const float* b2 = (const float*)d_in[5];
    float* out      = (float*)d_out;

    const int* src = ei;
    const int* dst = ei + N_EDGES;

    float* z; cudaGetSymbolAddress((void**)&z, g_z);

    // 1. zero accumulators (800k x 16B)
    zero_kernel<<<(2 * 400000 + 255) / 256, 256>>>();

    // 2. y = x @ W1 -> half2
    gemm_x_kernel<<<N_NODES / 50, 160>>>(x, W1);

    // 3. agg1h[dst] += yh[src]  (8 f16x2-v4 lanes per edge)
    scatter_h_kernel<<<N_EDGES * 8 / 256, 256>>>(src, dst);

    // 4. z = relu(agg1 + b1) @ W2
    hidden_kernel<<<(N_NODES + 63) / 64, 256>>>(b1, W2, z);

    // 5. agg2[dst] += z[src]  (8 f32-v4 lanes per edge)
    scatter_f_kernel<<<N_EDGES * 8 / 256, 256>>>(src, dst);

    // 6. out = log_softmax(agg2 + b2)
    lsm_kernel<<<N_NODES / 8, 256>>>(b2, out);
}

// round 9
// speedup vs baseline: 2.0721x; 1.1183x over previous
#include <cuda_runtime.h>
#include <cuda_fp16.h>

#define N_NODES 50000
#define N_EDGES 800000
#define IN_F 96
#define HID 64
#define N_CLS 32

// Scratch (__device__ globals, allocation-free rule)
__device__ __align__(16) unsigned g_yh[N_NODES * (HID / 2)];     // y half2     (6.4 MB)
__device__ __align__(16) unsigned g_agg1h[N_NODES * (HID / 2)];  // agg1 half2  (6.4 MB)
__device__ __align__(16) unsigned g_zh[N_NODES * (N_CLS / 2)];   // z half2     (3.2 MB)
__device__ __align__(16) unsigned g_agg2h[N_NODES * (N_CLS / 2)];// agg2 half2  (3.2 MB)

__device__ __forceinline__ void red_add_v4h2(unsigned* p, uint4 v) {
    asm volatile("red.global.add.noftz.v4.f16x2 [%0], {%1,%2,%3,%4};"
                 :: "l"(p), "r"(v.x), "r"(v.y), "r"(v.z), "r"(v.w) : "memory");
}

// Zero agg1h (400k uint4) + agg2h (200k uint4). 0x0000 == +0.0h.
__global__ void zero_kernel() {
    const int n1 = N_NODES * (HID / 2) / 4;    // 400000
    const int n2 = N_NODES * (N_CLS / 2) / 4;  // 200000
    int i = blockIdx.x * blockDim.x + threadIdx.x;
    if (i < n1) ((uint4*)g_agg1h)[i] = make_uint4(0u, 0u, 0u, 0u);
    else if (i < n1 + n2) ((uint4*)g_agg2h)[i - n1] = make_uint4(0u, 0u, 0u, 0u);
}

// y = x @ W1 [50000 x 64], output packed half2. 50 nodes/block, 160 threads,
// thread computes 5 nodes x 4 cols (= 2 half2).
__global__ void __launch_bounds__(160) gemm_x_kernel(
        const float* __restrict__ x,
        const float* __restrict__ W1) {
    __shared__ float xs[50 * 100];
    __shared__ float ws[IN_F * HID];
    int tid = threadIdx.x;

    for (int i = tid; i < IN_F * HID / 4; i += 160)
        ((float4*)ws)[i] = __ldg((const float4*)W1 + i);

    const float4* xg = (const float4*)x + blockIdx.x * 50 * (IN_F / 4);
    for (int i = tid; i < 50 * (IN_F / 4); i += 160) {
        int r = i / (IN_F / 4);
        int c = i - r * (IN_F / 4);
        *(float4*)&xs[r * 100 + c * 4] = __ldg(xg + i);
    }
    __syncthreads();

    int tx = tid & 15;
    int ty = tid >> 4;
    float acc[5][4];
#pragma unroll
    for (int i = 0; i < 5; ++i)
#pragma unroll
        for (int j = 0; j < 4; ++j) acc[i][j] = 0.f;

    const float* xbase = &xs[ty * 5 * 100];
#pragma unroll 2
    for (int k = 0; k < IN_F; k += 4) {
        float4 wv0 = *(float4*)&ws[(k + 0) * HID + tx * 4];
        float4 wv1 = *(float4*)&ws[(k + 1) * HID + tx * 4];
        float4 wv2 = *(float4*)&ws[(k + 2) * HID + tx * 4];
        float4 wv3 = *(float4*)&ws[(k + 3) * HID + tx * 4];
#pragma unroll
        for (int i = 0; i < 5; ++i) {
            float4 xv = *(float4*)&xbase[i * 100 + k];
            acc[i][0] = fmaf(xv.x, wv0.x, acc[i][0]);
            acc[i][1] = fmaf(xv.x, wv0.y, acc[i][1]);
            acc[i][2] = fmaf(xv.x, wv0.z, acc[i][2]);
            acc[i][3] = fmaf(xv.x, wv0.w, acc[i][3]);
            acc[i][0] = fmaf(xv.y, wv1.x, acc[i][0]);
            acc[i][1] = fmaf(xv.y, wv1.y, acc[i][1]);
            acc[i][2] = fmaf(xv.y, wv1.z, acc[i][2]);
            acc[i][3] = fmaf(xv.y, wv1.w, acc[i][3]);
            acc[i][0] = fmaf(xv.z, wv2.x, acc[i][0]);
            acc[i][1] = fmaf(xv.z, wv2.y, acc[i][1]);
            acc[i][2] = fmaf(xv.z, wv2.z, acc[i][2]);
            acc[i][3] = fmaf(xv.z, wv2.w, acc[i][3]);
            acc[i][0] = fmaf(xv.w, wv3.x, acc[i][0]);
            acc[i][1] = fmaf(xv.w, wv3.y, acc[i][1]);
            acc[i][2] = fmaf(xv.w, wv3.z, acc[i][2]);
            acc[i][3] = fmaf(xv.w, wv3.w, acc[i][3]);
        }
    }
    int n0 = blockIdx.x * 50 + ty * 5;
#pragma unroll
    for (int i = 0; i < 5; ++i) {
        __half2 h0 = __floats2half2_rn(acc[i][0], acc[i][1]);
        __half2 h1 = __floats2half2_rn(acc[i][2], acc[i][3]);
        uint2 u;
        u.x = *(unsigned*)&h0;
        u.y = *(unsigned*)&h1;
        *(uint2*)&g_yh[(n0 + i) * (HID / 2) + tx * 2] = u;
    }
}

// Layer-1 scatter: agg1h[dst] += yh[src]; 64 halves = 8 x uint4 lanes per edge.
__global__ void scatter1_kernel(const int* __restrict__ src,
                                const int* __restrict__ dst) {
    int i = blockIdx.x * blockDim.x + threadIdx.x;
    int e = i >> 3;
    int c = i & 7;
    int s = __ldg(src + e);
    int d = __ldg(dst + e);
    uint4 v = __ldg((const uint4*)g_yh + s * 8 + c);
    red_add_v4h2(g_agg1h + d * (HID / 2) + c * 4, v);
}

// Layer-2 scatter: agg2h[dst] += zh[src]; 32 halves = 4 x uint4 lanes per edge.
__global__ void scatter2_kernel(const int* __restrict__ src,
                                const int* __restrict__ dst) {
    int i = blockIdx.x * blockDim.x + threadIdx.x;
    int e = i >> 2;
    int c = i & 3;
    int s = __ldg(src + e);
    int d = __ldg(dst + e);
    uint4 v = __ldg((const uint4*)g_zh + s * 4 + c);
    red_add_v4h2(g_agg2h + d * (N_CLS / 2) + c * 4, v);
}

// z = relu(agg1 + b1) @ W2  [50000 x 32] -> half2. 64 nodes/block, 256 threads,
// 2x4 register tile. half2->float conversion + relu + bias fused in staging.
__global__ void __launch_bounds__(256) hidden_kernel(
        const float* __restrict__ b1,
        const float* __restrict__ W2) {
    __shared__ float as[64 * 68];      // 17408 B
    __shared__ float ws[HID * N_CLS];  // 8192 B
    int tid = threadIdx.x;

    for (int i = tid; i < HID * N_CLS / 4; i += 256)
        ((float4*)ws)[i] = __ldg((const float4*)W2 + i);

    int n0 = blockIdx.x * 64;
    for (int i = tid; i < 64 * 8; i += 256) {
        int r = i >> 3;
        int c = i & 7;
        int n = n0 + r;
        float4 f0 = make_float4(0.f, 0.f, 0.f, 0.f);
        float4 f1 = f0;
        if (n < N_NODES) {
            uint4 u = __ldg((const uint4*)g_agg1h + n * 8 + c);
            float2 a0 = __half22float2(*(__half2*)&u.x);
            float2 a1 = __half22float2(*(__half2*)&u.y);
            float2 a2 = __half22float2(*(__half2*)&u.z);
            float2 a3 = __half22float2(*(__half2*)&u.w);
            float4 bb0 = __ldg((const float4*)b1 + c * 2);
            float4 bb1 = __ldg((const float4*)b1 + c * 2 + 1);
            f0.x = fmaxf(a0.x + bb0.x, 0.f);
            f0.y = fmaxf(a0.y + bb0.y, 0.f);
            f0.z = fmaxf(a1.x + bb0.z, 0.f);
            f0.w = fmaxf(a1.y + bb0.w, 0.f);
            f1.x = fmaxf(a2.x + bb1.x, 0.f);
            f1.y = fmaxf(a2.y + bb1.y, 0.f);
            f1.z = fmaxf(a3.x + bb1.z, 0.f);
            f1.w = fmaxf(a3.y + bb1.w, 0.f);
        }
        *(float4*)&as[r * 68 + c * 8]     = f0;
        *(float4*)&as[r * 68 + c * 8 + 4] = f1;
    }
    __syncthreads();

    int tx = tid & 7;
    int ty = tid >> 3;
    float acc[2][4];
#pragma unroll
    for (int i = 0; i < 2; ++i)
#pragma unroll
        for (int j = 0; j < 4; ++j) acc[i][j] = 0.f;

    const float* abase = &as[ty * 2 * 68];
#pragma unroll 4
    for (int k = 0; k < HID; k += 4) {
        float4 wv0 = *(float4*)&ws[(k + 0) * N_CLS + tx * 4];
        float4 wv1 = *(float4*)&ws[(k + 1) * N_CLS + tx * 4];
        float4 wv2 = *(float4*)&ws[(k + 2) * N_CLS + tx * 4];
        float4 wv3 = *(float4*)&ws[(k + 3) * N_CLS + tx * 4];
#pragma unroll
        for (int i = 0; i < 2; ++i) {
            float4 xv = *(float4*)&abase[i * 68 + k];
            acc[i][0] = fmaf(xv.x, wv0.x, acc[i][0]);
            acc[i][1] = fmaf(xv.x, wv0.y, acc[i][1]);
            acc[i][2] = fmaf(xv.x, wv0.z, acc[i][2]);
            acc[i][3] = fmaf(xv.x, wv0.w, acc[i][3]);
            acc[i][0] = fmaf(xv.y, wv1.x, acc[i][0]);
            acc[i][1] = fmaf(xv.y, wv1.y, acc[i][1]);
            acc[i][2] = fmaf(xv.y, wv1.z, acc[i][2]);
            acc[i][3] = fmaf(xv.y, wv1.w, acc[i][3]);
            acc[i][0] = fmaf(xv.z, wv2.x, acc[i][0]);
            acc[i][1] = fmaf(xv.z, wv2.y, acc[i][1]);
            acc[i][2] = fmaf(xv.z, wv2.z, acc[i][2]);
            acc[i][3] = fmaf(xv.z, wv2.w, acc[i][3]);
            acc[i][0] = fmaf(xv.w, wv3.x, acc[i][0]);
            acc[i][1] = fmaf(xv.w, wv3.y, acc[i][1]);
            acc[i][2] = fmaf(xv.w, wv3.z, acc[i][2]);
            acc[i][3] = fmaf(xv.w, wv3.w, acc[i][3]);
        }
    }
#pragma unroll
    for (int i = 0; i < 2; ++i) {
        int n = n0 + ty * 2 + i;
        if (n < N_NODES) {
            __half2 h0 = __floats2half2_rn(acc[i][0], acc[i][1]);
            __half2 h1 = __floats2half2_rn(acc[i][2], acc[i][3]);
            uint2 u;
            u.x = *(unsigned*)&h0;
            u.y = *(unsigned*)&h1;
            *(uint2*)&g_zh[n * (N_CLS / 2) + tx * 2] = u;
        }
    }
}

// out = log_softmax(agg2 + b2). One warp per node (lane = class), 8 nodes/block.
__global__ void lsm_kernel(const float* __restrict__ b2,
                           float* __restrict__ out) {
    int lane = threadIdx.x & 31;
    int n = blockIdx.x * 8 + (threadIdx.x >> 5);
    const __half* ah = (const __half*)g_agg2h;
    float acc = __half2float(ah[n * N_CLS + lane]) + __ldg(b2 + lane);
    float m = acc;
#pragma unroll
    for (int o = 16; o; o >>= 1) m = fmaxf(m, __shfl_xor_sync(0xffffffffu, m, o));
    float p = __expf(acc - m);
#pragma unroll
    for (int o = 16; o; o >>= 1) p += __shfl_xor_sync(0xffffffffu, p, o);
    out[n * N_CLS + lane] = acc - m - __logf(p);
}

extern "C" void kernel_launch(void* const* d_in, const int* in_sizes, int n_in,
                              void* d_out, int out_size) {
    const float* x  = (const float*)d_in[0];
    const int*   ei = (const int*)d_in[1];   // int32 [2, E]
    const float* W1 = (const float*)d_in[2];
    const float* b1 = (const float*)d_in[3];
    const float* W2 = (const float*)d_in[4];
    const float* b2 = (const float*)d_in[5];
    float* out      = (float*)d_out;

    const int* src = ei;
    const int* dst = ei + N_EDGES;

    // 1. zero accumulators (600k x 16B)
    zero_kernel<<<(600000 + 255) / 256, 256>>>();

    // 2. y = x @ W1 -> half2
    gemm_x_kernel<<<N_NODES / 50, 160>>>(x, W1);

    // 3. agg1h[dst] += yh[src]  (8 f16x2-v4 lanes per edge)
    scatter1_kernel<<<N_EDGES * 8 / 256, 256>>>(src, dst);

    // 4. z = relu(agg1 + b1) @ W2 -> half2
    hidden_kernel<<<(N_NODES + 63) / 64, 256>>>(b1, W2);

    // 5. agg2h[dst] += zh[src]  (4 f16x2-v4 lanes per edge)
    scatter2_kernel<<<N_EDGES * 4 / 256, 256>>>(src, dst);

    // 6. out = log_softmax(agg2 + b2)
    lsm_kernel<<<N_NODES / 8, 256>>>(b2, out);
}

// round 10
// speedup vs baseline: 2.1293x; 1.0276x over previous
#include <cuda_runtime.h>
#include <cuda_fp16.h>

#define N_NODES 50000
#define N_EDGES 800000
#define IN_F 96
#define HID 64
#define N_CLS 32

// Scratch (__device__ globals, allocation-free rule)
__device__ __align__(16) unsigned g_yh[N_NODES * (HID / 2)];     // y half2     (6.4 MB)
__device__ __align__(16) unsigned g_agg1h[N_NODES * (HID / 2)];  // agg1 half2  (6.4 MB)
__device__ __align__(16) unsigned g_zh[N_NODES * (N_CLS / 2)];   // z half2     (3.2 MB)
__device__ __align__(16) unsigned g_agg2h[N_NODES * (N_CLS / 2)];// agg2 half2  (3.2 MB)

__device__ __forceinline__ void red_add_v4h2(unsigned* p, uint4 v) {
    asm volatile("red.global.add.noftz.v4.f16x2 [%0], {%1,%2,%3,%4};"
                 :: "l"(p), "r"(v.x), "r"(v.y), "r"(v.z), "r"(v.w) : "memory");
}

// Zero agg1h only (400k uint4); agg2h is zeroed inside hidden_kernel.
__global__ void zero_kernel() {
    const int n1 = N_NODES * (HID / 2) / 4;    // 400000
    int i = blockIdx.x * blockDim.x + threadIdx.x;
    if (i < n1) ((uint4*)g_agg1h)[i] = make_uint4(0u, 0u, 0u, 0u);
}

// y = x @ W1 [50000 x 64], output packed half2. 50 nodes/block, 160 threads,
// thread computes 5 nodes x 4 cols (= 2 half2).
__global__ void __launch_bounds__(160) gemm_x_kernel(
        const float* __restrict__ x,
        const float* __restrict__ W1) {
    __shared__ float xs[50 * 100];
    __shared__ float ws[IN_F * HID];
    int tid = threadIdx.x;

    for (int i = tid; i < IN_F * HID / 4; i += 160)
        ((float4*)ws)[i] = __ldg((const float4*)W1 + i);

    const float4* xg = (const float4*)x + blockIdx.x * 50 * (IN_F / 4);
    for (int i = tid; i < 50 * (IN_F / 4); i += 160) {
        int r = i / (IN_F / 4);
        int c = i - r * (IN_F / 4);
        *(float4*)&xs[r * 100 + c * 4] = __ldg(xg + i);
    }
    __syncthreads();

    int tx = tid & 15;
    int ty = tid >> 4;
    float acc[5][4];
#pragma unroll
    for (int i = 0; i < 5; ++i)
#pragma unroll
        for (int j = 0; j < 4; ++j) acc[i][j] = 0.f;

    const float* xbase = &xs[ty * 5 * 100];
#pragma unroll 2
    for (int k = 0; k < IN_F; k += 4) {
        float4 wv0 = *(float4*)&ws[(k + 0) * HID + tx * 4];
        float4 wv1 = *(float4*)&ws[(k + 1) * HID + tx * 4];
        float4 wv2 = *(float4*)&ws[(k + 2) * HID + tx * 4];
        float4 wv3 = *(float4*)&ws[(k + 3) * HID + tx * 4];
#pragma unroll
        for (int i = 0; i < 5; ++i) {
            float4 xv = *(float4*)&xbase[i * 100 + k];
            acc[i][0] = fmaf(xv.x, wv0.x, acc[i][0]);
            acc[i][1] = fmaf(xv.x, wv0.y, acc[i][1]);
            acc[i][2] = fmaf(xv.x, wv0.z, acc[i][2]);
            acc[i][3] = fmaf(xv.x, wv0.w, acc[i][3]);
            acc[i][0] = fmaf(xv.y, wv1.x, acc[i][0]);
            acc[i][1] = fmaf(xv.y, wv1.y, acc[i][1]);
            acc[i][2] = fmaf(xv.y, wv1.z, acc[i][2]);
            acc[i][3] = fmaf(xv.y, wv1.w, acc[i][3]);
            acc[i][0] = fmaf(xv.z, wv2.x, acc[i][0]);
            acc[i][1] = fmaf(xv.z, wv2.y, acc[i][1]);
            acc[i][2] = fmaf(xv.z, wv2.z, acc[i][2]);
            acc[i][3] = fmaf(xv.z, wv2.w, acc[i][3]);
            acc[i][0] = fmaf(xv.w, wv3.x, acc[i][0]);
            acc[i][1] = fmaf(xv.w, wv3.y, acc[i][1]);
            acc[i][2] = fmaf(xv.w, wv3.z, acc[i][2]);
            acc[i][3] = fmaf(xv.w, wv3.w, acc[i][3]);
        }
    }
    int n0 = blockIdx.x * 50 + ty * 5;
#pragma unroll
    for (int i = 0; i < 5; ++i) {
        __half2 h0 = __floats2half2_rn(acc[i][0], acc[i][1]);
        __half2 h1 = __floats2half2_rn(acc[i][2], acc[i][3]);
        uint2 u;
        u.x = *(unsigned*)&h0;
        u.y = *(unsigned*)&h1;
        *(uint2*)&g_yh[(n0 + i) * (HID / 2) + tx * 2] = u;
    }
}

// Layer-1 scatter: agg1h[dst] += yh[src]; 64 halves = 8 x uint4 lanes per edge.
__global__ void scatter1_kernel(const int* __restrict__ src,
                                const int* __restrict__ dst) {
    int i = blockIdx.x * blockDim.x + threadIdx.x;
    int e = i >> 3;
    int c = i & 7;
    int s = __ldg(src + e);
    int d = __ldg(dst + e);
    uint4 v = __ldg((const uint4*)g_yh + s * 8 + c);
    red_add_v4h2(g_agg1h + d * (HID / 2) + c * 4, v);
}

// Layer-2 scatter: agg2h[dst] += zh[src]; 32 halves = 4 x uint4 lanes per edge.
__global__ void scatter2_kernel(const int* __restrict__ src,
                                const int* __restrict__ dst) {
    int i = blockIdx.x * blockDim.x + threadIdx.x;
    int e = i >> 2;
    int c = i & 3;
    int s = __ldg(src + e);
    int d = __ldg(dst + e);
    uint4 v = __ldg((const uint4*)g_zh + s * 4 + c);
    red_add_v4h2(g_agg2h + d * (N_CLS / 2) + c * 4, v);
}

// z = relu(agg1 + b1) @ W2  [50000 x 32] -> half2. 64 nodes/block, 128 threads,
// thread computes a 4-node x 4-col register tile. Also zeroes agg2h slice.
__global__ void __launch_bounds__(128) hidden_kernel(
        const float* __restrict__ b1,
        const float* __restrict__ W2) {
    __shared__ float as[64 * 68];      // 17408 B
    __shared__ float ws[HID * N_CLS];  // 8192 B
    int tid = threadIdx.x;
    int n0 = blockIdx.x * 64;

    // fold: zero agg2h for this block's 64 nodes (4 uint4 per node).
    {
        int base = n0 * 4;               // uint4 index
        const int tot = N_NODES * 4;     // 200000
#pragma unroll
        for (int i = tid; i < 256; i += 128) {
            int j = base + i;
            if (j < tot) ((uint4*)g_agg2h)[j] = make_uint4(0u, 0u, 0u, 0u);
        }
    }

    for (int i = tid; i < HID * N_CLS / 4; i += 128)
        ((float4*)ws)[i] = __ldg((const float4*)W2 + i);

    // stage: 64 rows x 8 uint4 chunks; convert fp16->fp32, +b1, relu.
    for (int i = tid; i < 64 * 8; i += 128) {
        int r = i >> 3;
        int c = i & 7;
        int n = n0 + r;
        float4 f0 = make_float4(0.f, 0.f, 0.f, 0.f);
        float4 f1 = f0;
        if (n < N_NODES) {
            uint4 u = __ldg((const uint4*)g_agg1h + n * 8 + c);
            float2 a0 = __half22float2(*(__half2*)&u.x);
            float2 a1 = __half22float2(*(__half2*)&u.y);
            float2 a2 = __half22float2(*(__half2*)&u.z);
            float2 a3 = __half22float2(*(__half2*)&u.w);
            float4 bb0 = __ldg((const float4*)b1 + c * 2);
            float4 bb1 = __ldg((const float4*)b1 + c * 2 + 1);
            f0.x = fmaxf(a0.x + bb0.x, 0.f);
            f0.y = fmaxf(a0.y + bb0.y, 0.f);
            f0.z = fmaxf(a1.x + bb0.z, 0.f);
            f0.w = fmaxf(a1.y + bb0.w, 0.f);
            f1.x = fmaxf(a2.x + bb1.x, 0.f);
            f1.y = fmaxf(a2.y + bb1.y, 0.f);
            f1.z = fmaxf(a3.x + bb1.z, 0.f);
            f1.w = fmaxf(a3.y + bb1.w, 0.f);
        }
        *(float4*)&as[r * 68 + c * 8]     = f0;
        *(float4*)&as[r * 68 + c * 8 + 4] = f1;
    }
    __syncthreads();

    int tx = tid & 7;    // col group (8 x 4 cols = 32)
    int ty = tid >> 3;   // node group (0..15), 4 nodes each
    float acc[4][4];
#pragma unroll
    for (int i = 0; i < 4; ++i)
#pragma unroll
        for (int j = 0; j < 4; ++j) acc[i][j] = 0.f;

    const float* abase = &as[ty * 4 * 68];
#pragma unroll 2
    for (int k = 0; k < HID; k += 4) {
        float4 wv0 = *(float4*)&ws[(k + 0) * N_CLS + tx * 4];
        float4 wv1 = *(float4*)&ws[(k + 1) * N_CLS + tx * 4];
        float4 wv2 = *(float4*)&ws[(k + 2) * N_CLS + tx * 4];
        float4 wv3 = *(float4*)&ws[(k + 3) * N_CLS + tx * 4];
#pragma unroll
        for (int i = 0; i < 4; ++i) {
            float4 xv = *(float4*)&abase[i * 68 + k];
            acc[i][0] = fmaf(xv.x, wv0.x, acc[i][0]);
            acc[i][1] = fmaf(xv.x, wv0.y, acc[i][1]);
            acc[i][2] = fmaf(xv.x, wv0.z, acc[i][2]);
            acc[i][3] = fmaf(xv.x, wv0.w, acc[i][3]);
            acc[i][0] = fmaf(xv.y, wv1.x, acc[i][0]);
            acc[i][1] = fmaf(xv.y, wv1.y, acc[i][1]);
            acc[i][2] = fmaf(xv.y, wv1.z, acc[i][2]);
            acc[i][3] = fmaf(xv.y, wv1.w, acc[i][3]);
            acc[i][0] = fmaf(xv.z, wv2.x, acc[i][0]);
            acc[i][1] = fmaf(xv.z, wv2.y, acc[i][1]);
            acc[i][2] = fmaf(xv.z, wv2.z, acc[i][2]);
            acc[i][3] = fmaf(xv.z, wv2.w, acc[i][3]);
            acc[i][0] = fmaf(xv.w, wv3.x, acc[i][0]);
            acc[i][1] = fmaf(xv.w, wv3.y, acc[i][1]);
            acc[i][2] = fmaf(xv.w, wv3.z, acc[i][2]);
            acc[i][3] = fmaf(xv.w, wv3.w, acc[i][3]);
        }
    }
#pragma unroll
    for (int i = 0; i < 4; ++i) {
        int n = n0 + ty * 4 + i;
        if (n < N_NODES) {
            __half2 h0 = __floats2half2_rn(acc[i][0], acc[i][1]);
            __half2 h1 = __floats2half2_rn(acc[i][2], acc[i][3]);
            uint2 u;
            u.x = *(unsigned*)&h0;
            u.y = *(unsigned*)&h1;
            *(uint2*)&g_zh[n * (N_CLS / 2) + tx * 2] = u;
        }
    }
}

// out = log_softmax(agg2 + b2). One warp per node (lane = class), 8 nodes/block.
__global__ void lsm_kernel(const float* __restrict__ b2,
                           float* __restrict__ out) {
    int lane = threadIdx.x & 31;
    int n = blockIdx.x * 8 + (threadIdx.x >> 5);
    const __half* ah = (const __half*)g_agg2h;
    float acc = __half2float(ah[n * N_CLS + lane]) + __ldg(b2 + lane);
    float m = acc;
#pragma unroll
    for (int o = 16; o; o >>= 1) m = fmaxf(m, __shfl_xor_sync(0xffffffffu, m, o));
    float p = __expf(acc - m);
#pragma unroll
    for (int o = 16; o; o >>= 1) p += __shfl_xor_sync(0xffffffffu, p, o);
    out[n * N_CLS + lane] = acc - m - __logf(p);
}

extern "C" void kernel_launch(void* const* d_in, const int* in_sizes, int n_in,
                              void* d_out, int out_size) {
    const float* x  = (const float*)d_in[0];
    const int*   ei = (const int*)d_in[1];   // int32 [2, E]
    const float* W1 = (const float*)d_in[2];
    const float* b1 = (const float*)d_in[3];
    const float* W2 = (const float*)d_in[4];
    const float* b2 = (const float*)d_in[5];
    float* out      = (float*)d_out;

    const int* src = ei;
    const int* dst = ei + N_EDGES;

    // 1. zero agg1h (400k uint4)
    zero_kernel<<<(400000 + 255) / 256, 256>>>();

    // 2. y = x @ W1 -> half2
    gemm_x_kernel<<<N_NODES / 50, 160>>>(x, W1);

    // 3. agg1h[dst] += yh[src]  (8 f16x2-v4 lanes per edge)
    scatter1_kernel<<<N_EDGES * 8 / 256, 256>>>(src, dst);

    // 4. z = relu(agg1 + b1) @ W2 -> half2  (also zeroes agg2h)
    hidden_kernel<<<(N_NODES + 63) / 64, 128>>>(b1, W2);

    // 5. agg2h[dst] += zh[src]  (4 f16x2-v4 lanes per edge)
    scatter2_kernel<<<N_EDGES * 4 / 256, 256>>>(src, dst);

    // 6. out = log_softmax(agg2 + b2)
    lsm_kernel<<<N_NODES / 8, 256>>>(b2, out);
}